// round 7
// baseline (speedup 1.0000x reference)
#include <cuda_runtime.h>
#include <cuda_bf16.h>
#include <cuda_fp16.h>

// Problem constants (SwitchingGRU1: B=256, T=512, H=128, S=8, N_SWITCH=6)
#define BB   256
#define TT   512
#define HH   128
#define SS   8
#define NSW  6

// Swizzled fp16 weight scratch: 18 matrices of 128x128 = 590 KB.
// Layout per matrix m = g*NSW + s (g: 0=r,1=z,2=n), half-index:
//   dst[m*16384 + (j>>3)*1024 + i*8 + (j&7)] = (half)W_g[s][i][j]
// Thread i's float4 #jb (8 halves = cols 8jb..8jb+7 of row i) sits at
// float4-index m*2048 + jb*128 + i: consecutive lanes -> consecutive 16B.
__device__ __half g_wswz[3 * NSW * HH * HH];

__global__ void swz_kernel(const float* __restrict__ Wr,
                           const float* __restrict__ Wz,
                           const float* __restrict__ Wn) {
    int idx = blockIdx.x * blockDim.x + threadIdx.x;
    if (idx >= 3 * NSW * HH * HH) return;
    int m = idx >> 14;          // matrix id 0..17
    int r = idx & 16383;
    int i = r >> 7;             // row (output)
    int j = r & 127;            // col (input)
    int g = m / NSW;
    int s = m % NSW;
    const float* W = (g == 0) ? Wr : (g == 1) ? Wz : Wn;
    float v = W[s * HH * HH + i * HH + j];
    g_wswz[m * HH * HH + (j >> 3) * (8 * HH) + i * 8 + (j & 7)] = __float2half_rn(v);
}

// 384 threads: thread (g = tid>>7, i = tid&127) owns gate g, row i.
__global__ __launch_bounds__(384, 2) void gru_kernel(
    const float* __restrict__ stim,     // [B,T,S]
    const int*   __restrict__ swid,     // [B,T]
    const float* __restrict__ mask,     // [B,T]
    const float* __restrict__ Win,      // [3H,S]
    const float* __restrict__ bin_,     // [3H]
    const float* __restrict__ bhr,      // [NSW,H]
    const float* __restrict__ bhz,      // [NSW,H]
    const float* __restrict__ bhn,      // [NSW,H]
    const float* __restrict__ Wo,       // [2,H]
    const float* __restrict__ bo,       // [2]
    float*       __restrict__ out)      // [B,T,2]
{
    __shared__ __align__(16) float h_sh[HH];
    __shared__ float gz[HH];              // z pre-activation (gate 1)
    __shared__ float gn[HH];              // recurrent part of n (gate 2)
    __shared__ float gxn[HH];             // input part of n (gate 2)
    __shared__ float red[8];              // 4 warps x 2 logit partials
    __shared__ __align__(16) float stim_sm[TT * SS];   // 16 KB
    __shared__ int   sid_sm[TT];
    __shared__ float mask_sm[TT];

    const int b   = blockIdx.x;
    const int tid = threadIdx.x;
    const int g   = tid >> 7;     // 0=r, 1=z, 2=n
    const int i   = tid & 127;    // row within gate

    // ---- one-time staging: full sequence of stim/sid/mask for this batch ----
    {
        const float4* st4 = (const float4*)(stim + (size_t)b * TT * SS);
        float4* ss4 = (float4*)stim_sm;
        for (int e = tid; e < TT * SS / 4; e += 384) ss4[e] = st4[e];
        const int*   sb = swid + (size_t)b * TT;
        const float* mb = mask + (size_t)b * TT;
        for (int e = tid; e < TT; e += 384) {
            int s = sb[e];
            sid_sm[e]  = min(max(s, 0), NSW - 1);
            mask_sm[e] = mb[e];
        }
    }

    // ---- per-thread constants in registers ----
    float wv[SS];
#pragma unroll
    for (int s = 0; s < SS; s++) wv[s] = Win[tid * SS + s];   // row tid of Win
    const float bi = bin_[tid];
    const float* bhp = (g == 0) ? bhr : (g == 1) ? bhz : bhn;
    float bh_r[NSW];
#pragma unroll
    for (int s = 0; s < NSW; s++) bh_r[s] = bhp[s * HH + i];
    const float wo0 = Wo[i];          // used by g==0 only
    const float wo1 = Wo[HH + i];
    const float bo0 = __ldg(bo);
    const float bo1 = __ldg(bo + 1);

    float hreg = 0.0f;                // live only in g==0 threads
    if (g == 0) h_sh[i] = 0.0f;
    __syncthreads();

    // fp16 weights: each matrix = 2048 float4s; thread i starts at +i.
    const float4* __restrict__ Wgate =
        (const float4*)g_wswz + (size_t)g * NSW * 2048 + i;
    float* __restrict__ out_b = out + (size_t)b * TT * 2;

    for (int t = 0; t < TT; t++) {
        // ---- step t-1 logits: group 0 only, behind a NAMED barrier so
        //      groups 1/2 proceed straight to their weight loads ----
        if (g == 0 && t > 0) {
            float p0 = wo0 * hreg;
            float p1 = wo1 * hreg;
#pragma unroll
            for (int o = 16; o; o >>= 1) {
                p0 += __shfl_down_sync(0xffffffffu, p0, o);
                p1 += __shfl_down_sync(0xffffffffu, p1, o);
            }
            if ((tid & 31) == 0) { red[tid >> 5] = p0; red[4 + (tid >> 5)] = p1; }
            asm volatile("bar.sync 1, 128;" ::: "memory");
            if (tid == 0) out_b[2 * (t - 1)]     = red[0] + red[1] + red[2] + red[3] + bo0;
            if (tid == 1) out_b[2 * (t - 1) + 1] = red[4] + red[5] + red[6] + red[7] + bo1;
        }

        const int sid = sid_sm[t];

        // ---- input projection for this thread's gate row ----
        const float* sv = stim_sm + t * SS;
        float x = bi;
#pragma unroll
        for (int s = 0; s < SS; s++) x = fmaf(wv[s], sv[s], x);

        // ---- recurrent matvec: 16 independent coalesced LDG.128 (fp16 wts) ----
        float acc = bh_r[sid];
        const float4* __restrict__ W = Wgate + (size_t)sid * 2048;
        const float4* h4 = (const float4*)h_sh;
#pragma unroll
        for (int jb = 0; jb < 16; jb++) {
            float4 wraw = __ldg(W + jb * HH);
            const __half2* wh = (const __half2*)&wraw;
            float4 ha = h4[2 * jb];
            float4 hb = h4[2 * jb + 1];
            float2 w0 = __half22float2(wh[0]);
            float2 w1 = __half22float2(wh[1]);
            float2 w2 = __half22float2(wh[2]);
            float2 w3 = __half22float2(wh[3]);
            acc = fmaf(w0.x, ha.x, acc);
            acc = fmaf(w0.y, ha.y, acc);
            acc = fmaf(w1.x, ha.z, acc);
            acc = fmaf(w1.y, ha.w, acc);
            acc = fmaf(w2.x, hb.x, acc);
            acc = fmaf(w2.y, hb.y, acc);
            acc = fmaf(w3.x, hb.z, acc);
            acc = fmaf(w3.y, hb.w, acc);
        }

        if (g == 1)      gz[i]  = x + acc;        // z pre-activation
        else if (g == 2) { gn[i] = acc; gxn[i] = x; }  // n: keep parts split
        __syncthreads();   // sync#1: gate results visible; h_sh reads done

        if (g == 0) {
            float r = 1.0f / (1.0f + expf(-(x + acc)));
            float z = 1.0f / (1.0f + expf(-gz[i]));
            float n = tanhf(gxn[i] + r * gn[i]);
            float hnew = n + z * (hreg - n);          // (1-z)*n + z*h
            float m = mask_sm[t];
            hreg = hreg + m * (hnew - hreg);          // m*hnew + (1-m)*h
            h_sh[i] = hreg;
        }
        __syncthreads();   // sync#2: h(t) visible for next step
    }

    // ---- final step's logits ----
    if (g == 0) {
        float p0 = wo0 * hreg;
        float p1 = wo1 * hreg;
#pragma unroll
        for (int o = 16; o; o >>= 1) {
            p0 += __shfl_down_sync(0xffffffffu, p0, o);
            p1 += __shfl_down_sync(0xffffffffu, p1, o);
        }
        if ((tid & 31) == 0) { red[tid >> 5] = p0; red[4 + (tid >> 5)] = p1; }
        asm volatile("bar.sync 1, 128;" ::: "memory");
        if (tid == 0) out_b[2 * (TT - 1)]     = red[0] + red[1] + red[2] + red[3] + bo0;
        if (tid == 1) out_b[2 * (TT - 1) + 1] = red[4] + red[5] + red[6] + red[7] + bo1;
    }
}

extern "C" void kernel_launch(void* const* d_in, const int* in_sizes, int n_in,
                              void* d_out, int out_size) {
    const float* stim  = (const float*)d_in[0];
    const int*   swid  = (const int*)  d_in[1];
    const float* mask  = (const float*)d_in[2];
    const float* Win   = (const float*)d_in[3];
    const float* bin_  = (const float*)d_in[4];
    const float* W_hr  = (const float*)d_in[5];
    const float* W_hz  = (const float*)d_in[6];
    const float* W_hn  = (const float*)d_in[7];
    const float* b_hr  = (const float*)d_in[8];
    const float* b_hz  = (const float*)d_in[9];
    const float* b_hn  = (const float*)d_in[10];
    const float* Wo    = (const float*)d_in[11];
    const float* bo    = (const float*)d_in[12];
    float* out = (float*)d_out;

    const int total = 3 * NSW * HH * HH;
    swz_kernel<<<(total + 255) / 256, 256>>>(W_hr, W_hz, W_hn);
    gru_kernel<<<BB, 384>>>(stim, swid, mask, Win, bin_, b_hr, b_hz, b_hn,
                            Wo, bo, out);
}